// round 7
// baseline (speedup 1.0000x reference)
#include <cuda_runtime.h>
#include <cstdint>
#include <cfloat>

// YOLO detection postprocess:
//   in : (16, 25200, 85) f32   [xc, yc, w, h, conf, cls0..cls79]
//   out: (16, 25200, 6)  f32   [xmin, ymin, xmax, ymax, conf*maxcls, argmax] or zeros
//
// Block = 512 threads, 128 rows (4 threads/row, 20 classes each):
//   phase 1: coalesced float4 loads -> static smem tile (43520 B)
//   phase 2: 4-lane groups reduce one row; shfl_xor combine; lane q==0 writes.
// smem 43.5KB + 16 warps/block -> 4 blocks/SM = 64 warps (full occupancy).

#define CONF_THRESH 0.25f
#define ROW_LEN 85
#define OUT_LEN 6
#define ROWS_PER_BLOCK 128
#define THREADS 512
#define TILE_FLOATS (ROWS_PER_BLOCK * ROW_LEN)         // 10880
#define TILE_VEC4   (TILE_FLOATS / 4)                  // 2720
#define FULL_ITERS  (TILE_VEC4 / THREADS)              // 5
#define REM_VECS    (TILE_VEC4 - FULL_ITERS * THREADS) // 160

__global__ __launch_bounds__(THREADS) void yolo_post_kernel(
    const float* __restrict__ in, float* __restrict__ out, int nrows)
{
    __shared__ float tile[TILE_FLOATS];

    const int tid  = threadIdx.x;
    const int row0 = blockIdx.x * ROWS_PER_BLOCK;

    // ---- Phase 1: coalesced vectorized load of 128 rows into smem ----
    {
        const float4* src = reinterpret_cast<const float4*>(in + (size_t)row0 * ROW_LEN);
        float4* dst = reinterpret_cast<float4*>(tile);
#pragma unroll
        for (int i = 0; i < FULL_ITERS; i++)
            dst[tid + i * THREADS] = src[tid + i * THREADS];
        if (tid < REM_VECS)
            dst[tid + FULL_ITERS * THREADS] = src[tid + FULL_ITERS * THREADS];
    }
    __syncthreads();

    // ---- Phase 2: 4 threads per row ----
    const int r = tid >> 2;        // row within block (0..127)
    const int q = tid & 3;         // quarter (0..3), classes [20q, 20q+20)
    const float* rp = tile + r * ROW_LEN;
    const float* cp = rp + 5 + 20 * q;

    float best = cp[0];
    int   bidx = 20 * q;
#pragma unroll 4
    for (int c = 1; c < 20; c++) {
        const float v = cp[c];
        if (v > best) { best = v; bidx = 20 * q + c; }  // strict > : first max
    }

    // Combine across the 4-lane group; tie -> lowest class index (jnp.argmax)
#pragma unroll
    for (int off = 1; off <= 2; off <<= 1) {
        const float ob = __shfl_xor_sync(0xffffffffu, best, off);
        const int   oi = __shfl_xor_sync(0xffffffffu, bidx, off);
        if (ob > best || (ob == best && oi < bidx)) { best = ob; bidx = oi; }
    }

    if (q == 0) {
        const float x = rp[0], y = rp[1], w = rp[2], h = rp[3], conf = rp[4];
        const float score = conf * best;
        const bool  keep  = score > CONF_THRESH;
        const float hw = 0.5f * w;
        const float hh = 0.5f * h;

        float2 o0, o1, o2;
        if (keep) {
            o0 = make_float2(x - hw, y - hh);
            o1 = make_float2(x + hw, y + hh);
            o2 = make_float2(score, (float)bidx);
        } else {
            o0 = make_float2(0.f, 0.f);
            o1 = make_float2(0.f, 0.f);
            o2 = make_float2(0.f, 0.f);
        }

        float2* orow = reinterpret_cast<float2*>(out + (size_t)(row0 + r) * OUT_LEN);
        orow[0] = o0;
        orow[1] = o1;
        orow[2] = o2;
    }
}

extern "C" void kernel_launch(void* const* d_in, const int* in_sizes, int n_in,
                              void* d_out, int out_size)
{
    const float* in  = (const float*)d_in[0];
    float*       out = (float*)d_out;

    const int nrows  = in_sizes[0] / ROW_LEN;         // 403200
    const int blocks = nrows / ROWS_PER_BLOCK;        // 3150 (exact)

    yolo_post_kernel<<<blocks, THREADS>>>(in, out, nrows);
}

// round 8
// speedup vs baseline: 1.1851x; 1.1851x over previous
#include <cuda_runtime.h>
#include <cstdint>

// YOLO detection postprocess:
//   in : (16, 25200, 85) f32   [xc, yc, w, h, conf, cls0..cls79]
//   out: (16, 25200, 6)  f32   [xmin, ymin, xmax, ymax, conf*maxcls, argmax] or zeros
//
// Persistent blocks, cp.async.cg double-buffered pipeline:
//   - 64 rows/tile (21760 B), 2 stages = 43520 B static smem -> 5 blocks/SM
//   - while computing tile t (1 thread/row, stride-85 conflict-free LDS),
//     cp.async prefetches tile t+step; DRAM streams continuously.

#define CONF_THRESH 0.25f
#define ROW_LEN 85
#define OUT_LEN 6
#define ROWS 64
#define THREADS 64
#define TILE_FLOATS (ROWS * ROW_LEN)            // 5440
#define TILE_VEC4   (TILE_FLOATS / 4)           // 1360
#define VEC_FULL    (TILE_VEC4 / THREADS)       // 21
#define VEC_REM     (TILE_VEC4 - VEC_FULL * THREADS) // 16

__device__ __forceinline__ void cp16(uint32_t dst_smem, const void* src_gmem) {
    asm volatile("cp.async.cg.shared.global [%0], [%1], 16;\n"
                 :: "r"(dst_smem), "l"(src_gmem));
}

__global__ __launch_bounds__(THREADS) void yolo_post_kernel(
    const float* __restrict__ in, float* __restrict__ out, int ntiles)
{
    __shared__ __align__(16) float buf[2][TILE_FLOATS];

    const int tid  = threadIdx.x;
    const int step = gridDim.x;

    uint32_t sbase[2];
    sbase[0] = (uint32_t)__cvta_generic_to_shared(buf[0]);
    sbase[1] = (uint32_t)__cvta_generic_to_shared(buf[1]);

    int tile = blockIdx.x;

    // Prologue: prefetch first tile into stage 0
    if (tile < ntiles) {
        const float4* src = (const float4*)(in + (size_t)tile * TILE_FLOATS);
#pragma unroll
        for (int i = 0; i < VEC_FULL; i++)
            cp16(sbase[0] + (uint32_t)(tid + i * THREADS) * 16, src + tid + i * THREADS);
        if (tid < VEC_REM)
            cp16(sbase[0] + (uint32_t)(tid + VEC_FULL * THREADS) * 16,
                 src + tid + VEC_FULL * THREADS);
    }
    asm volatile("cp.async.commit_group;\n");

    int stage = 0;
    while (tile < ntiles) {
        // Prefetch next tile into the other stage (may be an empty group at tail)
        const int next = tile + step;
        if (next < ntiles) {
            const float4* src = (const float4*)(in + (size_t)next * TILE_FLOATS);
            const uint32_t db = sbase[stage ^ 1];
#pragma unroll
            for (int i = 0; i < VEC_FULL; i++)
                cp16(db + (uint32_t)(tid + i * THREADS) * 16, src + tid + i * THREADS);
            if (tid < VEC_REM)
                cp16(db + (uint32_t)(tid + VEC_FULL * THREADS) * 16,
                     src + tid + VEC_FULL * THREADS);
        }
        asm volatile("cp.async.commit_group;\n");

        // Wait for current tile's group (allow the just-issued prefetch to fly)
        asm volatile("cp.async.wait_group 1;\n");
        __syncthreads();

        // ---- Compute: one thread per row, conflict-free stride-85 LDS ----
        const float* r = buf[stage] + tid * ROW_LEN;

        const float x = r[0], y = r[1], w = r[2], h = r[3], conf = r[4];

        float best = r[5];
        int   bidx = 0;
#pragma unroll 4
        for (int c = 1; c < 80; c++) {
            const float v = r[5 + c];
            if (v > best) { best = v; bidx = c; }   // strict > : first max (jnp.argmax)
        }

        const float score = conf * best;
        const bool  keep  = score > CONF_THRESH;
        const float hw = 0.5f * w;
        const float hh = 0.5f * h;

        float2 o0, o1, o2;
        if (keep) {
            o0 = make_float2(x - hw, y - hh);
            o1 = make_float2(x + hw, y + hh);
            o2 = make_float2(score, (float)bidx);
        } else {
            o0 = make_float2(0.f, 0.f);
            o1 = make_float2(0.f, 0.f);
            o2 = make_float2(0.f, 0.f);
        }

        float2* orow = reinterpret_cast<float2*>(out + (size_t)(tile * ROWS + tid) * OUT_LEN);
        orow[0] = o0;
        orow[1] = o1;
        orow[2] = o2;

        // All threads done reading buf[stage] before the next iteration's
        // prefetch overwrites it.
        __syncthreads();

        tile = next;
        stage ^= 1;
    }
}

extern "C" void kernel_launch(void* const* d_in, const int* in_sizes, int n_in,
                              void* d_out, int out_size)
{
    const float* in  = (const float*)d_in[0];
    float*       out = (float*)d_out;

    const int nrows  = in_sizes[0] / ROW_LEN;     // 403200
    const int ntiles = nrows / ROWS;              // 6300 (exact)

    // Persistent grid: 5 blocks/SM x 148 SMs
    const int blocks = 740;

    yolo_post_kernel<<<blocks, THREADS>>>(in, out, ntiles);
}

// round 10
// speedup vs baseline: 1.3618x; 1.1491x over previous
#include <cuda_runtime.h>
#include <cstdint>

// YOLO detection postprocess:
//   in : (16, 25200, 85) f32   [xc, yc, w, h, conf, cls0..cls79]
//   out: (16, 25200, 6)  f32   [xmin, ymin, xmax, ymax, conf*maxcls, argmax] or zeros
//
// Persistent blocks, cp.async.cg double-buffered pipeline:
//   - 64 rows/tile (21760 B), 2 stages = 43520 B static smem -> 5 blocks/SM
//   - 128 threads: 2 threads/row (40 classes each, conflict-free stride-85 LDS),
//     two interleaved max-chains, shfl_xor(1) pair combine.

#define CONF_THRESH 0.25f
#define ROW_LEN 85
#define OUT_LEN 6
#define ROWS 64
#define THREADS 128
#define TILE_FLOATS (ROWS * ROW_LEN)                 // 5440
#define TILE_VEC4   (TILE_FLOATS / 4)                // 1360
#define VEC_FULL    (TILE_VEC4 / THREADS)            // 10
#define VEC_REM     (TILE_VEC4 - VEC_FULL * THREADS) // 80

__device__ __forceinline__ void cp16(uint32_t dst_smem, const void* src_gmem) {
    asm volatile("cp.async.cg.shared.global [%0], [%1], 16;\n"
                 :: "r"(dst_smem), "l"(src_gmem));
}

__device__ __forceinline__ void prefetch_tile(uint32_t sb, const float* __restrict__ in,
                                              int tile, int tid)
{
    const float4* src = (const float4*)(in + (size_t)tile * TILE_FLOATS);
#pragma unroll
    for (int i = 0; i < VEC_FULL; i++)
        cp16(sb + (uint32_t)(tid + i * THREADS) * 16, src + tid + i * THREADS);
    if (tid < VEC_REM)
        cp16(sb + (uint32_t)(tid + VEC_FULL * THREADS) * 16,
             src + tid + VEC_FULL * THREADS);
}

__global__ __launch_bounds__(THREADS) void yolo_post_kernel(
    const float* __restrict__ in, float* __restrict__ out, int ntiles)
{
    __shared__ __align__(16) float buf[2][TILE_FLOATS];

    const int tid  = threadIdx.x;
    const int step = gridDim.x;

    uint32_t sbase[2];
    sbase[0] = (uint32_t)__cvta_generic_to_shared(buf[0]);
    sbase[1] = (uint32_t)__cvta_generic_to_shared(buf[1]);

    int tile = blockIdx.x;

    // Prologue: prefetch first tile into stage 0
    if (tile < ntiles)
        prefetch_tile(sbase[0], in, tile, tid);
    asm volatile("cp.async.commit_group;\n");

    const int r = tid >> 1;          // row within tile (0..63)
    const int q = tid & 1;           // half: classes [40q, 40q+40)

    int stage = 0;
    while (tile < ntiles) {
        // Prefetch next tile into the other stage
        const int next = tile + step;
        if (next < ntiles)
            prefetch_tile(sbase[stage ^ 1], in, next, tid);
        asm volatile("cp.async.commit_group;\n");

        // Wait for current tile (the just-issued prefetch keeps flying)
        asm volatile("cp.async.wait_group 1;\n");
        __syncthreads();

        // ---- Compute: 2 threads per row ----
        const float* rp = buf[stage] + r * ROW_LEN;
        const float* cp = rp + 5 + 40 * q;

        // Two interleaved chains (even/odd) to halve the dependent-max depth.
        float b0 = cp[0]; int i0 = 0;
        float b1 = cp[1]; int i1 = 1;
#pragma unroll
        for (int c = 2; c < 40; c += 2) {
            const float v0 = cp[c];
            const float v1 = cp[c + 1];
            if (v0 > b0) { b0 = v0; i0 = c; }       // strict > : first max
            if (v1 > b1) { b1 = v1; i1 = c + 1; }
        }
        // Merge chains: tie -> lower index (even chain has lower idx on ties)
        float best; int bidx;
        if (b1 > b0) { best = b1; bidx = i1; } else { best = b0; bidx = i0; }
        bidx += 40 * q;

        // Combine across the lane pair; tie -> lowest class index (jnp.argmax)
        {
            const float ob = __shfl_xor_sync(0xffffffffu, best, 1);
            const int   oi = __shfl_xor_sync(0xffffffffu, bidx, 1);
            if (ob > best || (ob == best && oi < bidx)) { best = ob; bidx = oi; }
        }

        const float x = rp[0], y = rp[1], w = rp[2], h = rp[3], conf = rp[4];
        const float score = conf * best;
        const bool  keep  = score > CONF_THRESH;
        const float hw = 0.5f * w;
        const float hh = 0.5f * h;

        float2* orow = reinterpret_cast<float2*>(out + (size_t)(tile * ROWS + r) * OUT_LEN);
        if (q == 0) {
            orow[0] = keep ? make_float2(x - hw, y - hh) : make_float2(0.f, 0.f);
            orow[1] = keep ? make_float2(x + hw, y + hh) : make_float2(0.f, 0.f);
        } else {
            orow[2] = keep ? make_float2(score, (float)bidx) : make_float2(0.f, 0.f);
        }

        // All threads done reading buf[stage] before next prefetch overwrites it.
        __syncthreads();

        tile = next;
        stage ^= 1;
    }
}

extern "C" void kernel_launch(void* const* d_in, const int* in_sizes, int n_in,
                              void* d_out, int out_size)
{
    const float* in  = (const float*)d_in[0];
    float*       out = (float*)d_out;

    const int nrows  = in_sizes[0] / ROW_LEN;     // 403200
    const int ntiles = nrows / ROWS;              // 6300 (exact)

    // Persistent grid: 5 blocks/SM x 148 SMs
    const int blocks = 740;

    yolo_post_kernel<<<blocks, THREADS>>>(in, out, ntiles);
}